// round 1
// baseline (speedup 1.0000x reference)
#include <cuda_runtime.h>

// Problem constants
#define N_TOK   16384          // B*S = 32*512
#define D_DIM   256
#define K_SUB   3686           // NUM_TOKENS * (1 - 0.1)
#define K_PAD   3712           // 29 * 128
#define NKT     29             // K_PAD / 128
#define T_SPLIT0 15            // k-tiles in split 0 (split 1 gets 14)
#define OUT_TOKENS  (N_TOK * D_DIM)     // 4194304 floats
#define OUT_LOSS    OUT_TOKENS          // index of loss scalar
#define OUT_IDX     (OUT_TOKENS + 1)    // start of indices (as float)

// ---------------- device scratch (no allocations allowed) ----------------
__device__ __align__(16) float g_sub[K_PAD * D_DIM];   // gathered sub-codebook, padded
__device__ float g_c2[K_PAD];                          // ||c||^2 per sub row (pad = +huge)
__device__ float g_bestd[2 * N_TOK];                   // per-k-split best distance
__device__ int   g_besti[2 * N_TOK];                   // per-k-split best local k
__device__ int   g_fidx[N_TOK];                        // final codebook row per token
__device__ float g_partial[1024];                      // loss partial sums

// ---------------- kernel 1: gather sub-codebook + row norms ----------------
__global__ void k_prep(const float* __restrict__ cb, const int* __restrict__ rnd) {
    int k = blockIdx.x;          // 0..K_PAD-1
    int t = threadIdx.x;         // 64 threads, float4 each = 256 floats
    __shared__ float ssum[2];
    if (k < K_SUB) {
        int row = rnd[k];
        float4 v = ((const float4*)(cb + (size_t)row * D_DIM))[t];
        ((float4*)(g_sub + (size_t)k * D_DIM))[t] = v;
        float s = v.x*v.x + v.y*v.y + v.z*v.z + v.w*v.w;
        #pragma unroll
        for (int o = 16; o; o >>= 1) s += __shfl_down_sync(0xffffffffu, s, o);
        if ((t & 31) == 0) ssum[t >> 5] = s;
        __syncthreads();
        if (t == 0) g_c2[k] = ssum[0] + ssum[1];
    } else {
        ((float4*)(g_sub + (size_t)k * D_DIM))[t] = make_float4(0.f, 0.f, 0.f, 0.f);
        if (t == 0) g_c2[k] = 3.0e38f;   // never selected
    }
}

// ---------------- kernel 2: fused GEMM + argmin ----------------
// 128x128 tile, 256 threads, 8x8 micro-tile, D chunked by 8, double-buffered smem.
// grid = (128 token tiles, 2 k-splits)
__global__ void __launch_bounds__(256) k_gemm(const float* __restrict__ x) {
    __shared__ float xs[2][8][132];   // [buf][d][token], padded to kill STS conflicts
    __shared__ float cs[2][8][132];   // [buf][d][cand]
    __shared__ float c2s[128];

    const int tid = threadIdx.x;
    const int tx = tid & 15;          // candidate-dim thread coord
    const int ty = tid >> 4;          // token-dim thread coord
    const int tokBase = blockIdx.x * 128;
    const int split = blockIdx.y;
    const int kt0 = split * T_SPLIT0;
    const int kt1 = split ? NKT : T_SPLIT0;

    const int lrow  = tid >> 1;          // 0..127: row loaded by this thread
    const int lcol4 = (tid & 1) * 4;     // 0 or 4: d-offset within 8-chunk

    const float* xrow = x + (size_t)(tokBase + lrow) * D_DIM + lcol4;

    float bestd[8];
    int   besti[8];
    #pragma unroll
    for (int i = 0; i < 8; i++) { bestd[i] = 3.4e38f; besti[i] = 0; }

    #pragma unroll 1
    for (int kt = kt0; kt < kt1; ++kt) {
        const int kBase = kt * 128;
        const float* crow = g_sub + (size_t)(kBase + lrow) * D_DIM + lcol4;

        float acc[8][8];
        #pragma unroll
        for (int i = 0; i < 8; i++)
            #pragma unroll
            for (int j = 0; j < 8; j++) acc[i][j] = 0.f;

        if (tid < 128) c2s[tid] = g_c2[kBase + tid];

        // prefetch d-chunk 0
        {
            float4 vx = *(const float4*)xrow;
            float4 vc = *(const float4*)crow;
            xs[0][lcol4 + 0][lrow] = vx.x; xs[0][lcol4 + 1][lrow] = vx.y;
            xs[0][lcol4 + 2][lrow] = vx.z; xs[0][lcol4 + 3][lrow] = vx.w;
            cs[0][lcol4 + 0][lrow] = vc.x; cs[0][lcol4 + 1][lrow] = vc.y;
            cs[0][lcol4 + 2][lrow] = vc.z; cs[0][lcol4 + 3][lrow] = vc.w;
        }
        __syncthreads();

        int buf = 0;
        #pragma unroll 1
        for (int dc = 0; dc < 32; ++dc) {
            float4 nx, nc;
            if (dc < 31) {
                nx = *(const float4*)(xrow + (dc + 1) * 8);
                nc = *(const float4*)(crow + (dc + 1) * 8);
            }
            #pragma unroll
            for (int kk = 0; kk < 8; ++kk) {
                float a[8], b[8];
                float4 a0 = *(const float4*)&xs[buf][kk][ty * 4];
                float4 a1 = *(const float4*)&xs[buf][kk][64 + ty * 4];
                float4 b0 = *(const float4*)&cs[buf][kk][tx * 4];
                float4 b1 = *(const float4*)&cs[buf][kk][64 + tx * 4];
                a[0]=a0.x; a[1]=a0.y; a[2]=a0.z; a[3]=a0.w;
                a[4]=a1.x; a[5]=a1.y; a[6]=a1.z; a[7]=a1.w;
                b[0]=b0.x; b[1]=b0.y; b[2]=b0.z; b[3]=b0.w;
                b[4]=b1.x; b[5]=b1.y; b[6]=b1.z; b[7]=b1.w;
                #pragma unroll
                for (int i = 0; i < 8; i++)
                    #pragma unroll
                    for (int j = 0; j < 8; j++)
                        acc[i][j] += a[i] * b[j];
            }
            if (dc < 31) {
                int nb = buf ^ 1;
                xs[nb][lcol4 + 0][lrow] = nx.x; xs[nb][lcol4 + 1][lrow] = nx.y;
                xs[nb][lcol4 + 2][lrow] = nx.z; xs[nb][lcol4 + 3][lrow] = nx.w;
                cs[nb][lcol4 + 0][lrow] = nc.x; cs[nb][lcol4 + 1][lrow] = nc.y;
                cs[nb][lcol4 + 2][lrow] = nc.z; cs[nb][lcol4 + 3][lrow] = nc.w;
            }
            __syncthreads();
            buf ^= 1;
        }

        // epilogue: dist = ||c||^2 - 2 * dot  (||x||^2 is argmin-invariant)
        #pragma unroll
        for (int jg = 0; jg < 2; jg++)
            #pragma unroll
            for (int j = 0; j < 4; j++) {
                int col = jg * 64 + tx * 4 + j;
                float c2v = c2s[col];
                int kg = kBase + col;
                #pragma unroll
                for (int i8 = 0; i8 < 8; i8++) {
                    float dm = c2v - 2.0f * acc[i8][jg * 4 + j];
                    if (dm < bestd[i8] || (dm == bestd[i8] && kg < besti[i8])) {
                        bestd[i8] = dm; besti[i8] = kg;
                    }
                }
            }
        __syncthreads();   // protect c2s before next tile overwrites it
    }

    // reduce argmin across tx (16 lanes within half-warp; xor offsets <= 8 stay inside)
    #pragma unroll
    for (int i8 = 0; i8 < 8; i8++) {
        float d = bestd[i8];
        int   bi = besti[i8];
        #pragma unroll
        for (int o = 8; o; o >>= 1) {
            float od = __shfl_xor_sync(0xffffffffu, d, o);
            int   oi = __shfl_xor_sync(0xffffffffu, bi, o);
            if (od < d || (od == d && oi < bi)) { d = od; bi = oi; }
        }
        if (tx == 0) {
            int r = (i8 < 4) ? (ty * 4 + i8) : (64 + ty * 4 + (i8 - 4));
            g_bestd[split * N_TOK + tokBase + r] = d;
            g_besti[split * N_TOK + tokBase + r] = bi;
        }
    }
}

// ---------------- kernel 3: merge k-splits, resolve codebook index ----------------
__global__ void k_merge(const int* __restrict__ rnd, float* __restrict__ out) {
    int t = blockIdx.x * 256 + threadIdx.x;
    if (t < N_TOK) {
        float d0 = g_bestd[t], d1 = g_bestd[N_TOK + t];
        int   i0 = g_besti[t], i1 = g_besti[N_TOK + t];
        int kbest = (d1 < d0 || (d1 == d0 && i1 < i0)) ? i1 : i0;
        int ci = rnd[kbest];
        g_fidx[t] = ci;
        out[OUT_IDX + t] = (float)ci;
    }
}

// ---------------- kernel 4: gather closest tokens + loss partials ----------------
__global__ void k_gather(const float* __restrict__ x, const float* __restrict__ cb,
                         float* __restrict__ out) {
    __shared__ float red[256];
    int tid = threadIdx.x;
    float s = 0.f;
    #pragma unroll
    for (int j = 0; j < 4; j++) {
        int f = blockIdx.x * 1024 + j * 256 + tid;   // float4 index
        int tok = f >> 6;
        int off = f & 63;
        int ci = g_fidx[tok];
        float4 c = ((const float4*)cb)[(size_t)ci * 64 + off];
        float4 xv = ((const float4*)x)[f];
        ((float4*)out)[f] = c;
        float dx = c.x - xv.x, dy = c.y - xv.y, dz = c.z - xv.z, dw = c.w - xv.w;
        s += dx * dx + dy * dy + dz * dz + dw * dw;
    }
    red[tid] = s;
    __syncthreads();
    for (int o = 128; o; o >>= 1) {
        if (tid < o) red[tid] += red[tid + o];
        __syncthreads();
    }
    if (tid == 0) g_partial[blockIdx.x] = red[0];
}

// ---------------- kernel 5: final deterministic loss reduce ----------------
__global__ void k_loss(float* __restrict__ out) {
    __shared__ float red[256];
    int tid = threadIdx.x;
    float s = 0.f;
    for (int j = tid; j < 1024; j += 256) s += g_partial[j];
    red[tid] = s;
    __syncthreads();
    for (int o = 128; o; o >>= 1) {
        if (tid < o) red[tid] += red[tid + o];
        __syncthreads();
    }
    if (tid == 0) out[OUT_LOSS] = red[0] / (float)OUT_TOKENS;
}

// ---------------- launch ----------------
extern "C" void kernel_launch(void* const* d_in, const int* in_sizes, int n_in,
                              void* d_out, int out_size) {
    const float* x   = (const float*)d_in[0];   // [32,512,256] f32
    const float* cb  = (const float*)d_in[1];   // [4096,256]   f32
    const int*   rnd = (const int*)d_in[2];     // [3686]       i32
    float* out = (float*)d_out;

    k_prep<<<K_PAD, 64>>>(cb, rnd);
    k_gemm<<<dim3(128, 2), 256>>>(x);
    k_merge<<<64, 256>>>(rnd, out);
    k_gather<<<1024, 256>>>(x, cb, out);
    k_loss<<<1, 256>>>(out);
}

// round 3
// speedup vs baseline: 3.2372x; 3.2372x over previous
#include <cuda_runtime.h>
#include <cuda_fp16.h>
#include <cstdint>

// ---------------- problem constants ----------------
#define N_TOK   16384          // B*S
#define D_DIM   256
#define K_SUB   3686
#define K_PAD   3840           // 30 * 128
#define N_YT    30             // candidate tiles of 128
#define KP      768            // virtual K: [xh|xh|xl] . [ch|cl|ch]
#define OUT_TOKENS  (N_TOK * D_DIM)
#define OUT_LOSS    OUT_TOKENS
#define OUT_IDX     (OUT_TOKENS + 1)

// ---------------- device scratch ----------------
__device__ __align__(16) __half g_xb[N_TOK * KP];    // 25.2 MB
__device__ __align__(16) __half g_cb2[K_PAD * KP];   // 5.9 MB
__device__ float g_c2[K_PAD];
__device__ float g_bestd[N_YT * N_TOK];
__device__ int   g_besti[N_YT * N_TOK];
__device__ int   g_fidx[N_TOK];
__device__ float g_partial[1024];

// ---------------- PTX helpers ----------------
__device__ __forceinline__ uint32_t smem_u32(const void* p) {
    uint32_t a;
    asm("{ .reg .u64 t; cvta.to.shared.u64 t, %1; cvt.u32.u64 %0, t; }" : "=r"(a) : "l"(p));
    return a;
}
__device__ __forceinline__ void cpa16(uint32_t dst, const void* src) {
    asm volatile("cp.async.cg.shared.global [%0], [%1], 16;" :: "r"(dst), "l"(src));
}
#define CP_COMMIT() asm volatile("cp.async.commit_group;" ::: "memory")
#define CP_WAIT(n)  asm volatile("cp.async.wait_group %0;" :: "n"(n) : "memory")

__device__ __forceinline__ void ldsm4(uint32_t* r, uint32_t a) {
    asm volatile("ldmatrix.sync.aligned.m8n8.x4.shared.b16 {%0,%1,%2,%3}, [%4];"
        : "=r"(r[0]), "=r"(r[1]), "=r"(r[2]), "=r"(r[3]) : "r"(a));
}
__device__ __forceinline__ void mma16816(float* c, const uint32_t* a,
                                         uint32_t b0, uint32_t b1) {
    asm volatile("mma.sync.aligned.m16n8k16.row.col.f32.f16.f16.f32 "
        "{%0,%1,%2,%3}, {%4,%5,%6,%7}, {%8,%9}, {%0,%1,%2,%3};"
        : "+f"(c[0]), "+f"(c[1]), "+f"(c[2]), "+f"(c[3])
        : "r"(a[0]), "r"(a[1]), "r"(a[2]), "r"(a[3]), "r"(b0), "r"(b1));
}

// ---------------- kernel 1a: split x -> fp16 hi/lo, build A'' = [xh|xh|xl] ----
__global__ void k_prep_x(const float* __restrict__ x) {
    int i = blockIdx.x * 256 + threadIdx.x;       // float4 index (1M)
    int tok = i >> 6, d4 = i & 63;
    float4 v = ((const float4*)x)[i];
    __half hx = __float2half_rn(v.x), hy = __float2half_rn(v.y);
    __half hz = __float2half_rn(v.z), hw = __float2half_rn(v.w);
    __half lx = __float2half_rn(v.x - __half2float(hx));
    __half ly = __float2half_rn(v.y - __half2float(hy));
    __half lz = __float2half_rn(v.z - __half2float(hz));
    __half lw = __float2half_rn(v.w - __half2float(hw));
    __half2 h0 = __halves2half2(hx, hy), h1 = __halves2half2(hz, hw);
    __half2 l0 = __halves2half2(lx, ly), l1 = __halves2half2(lz, lw);
    __half2* base = (__half2*)(g_xb + (size_t)tok * KP + d4 * 4);
    base[0] = h0; base[1] = h1;                       // cols [0,256): xh
    base[128] = h0; base[129] = h1;                   // cols [256,512): xh
    base[256] = l0; base[257] = l1;                   // cols [512,768): xl
}

// ---- kernel 1b: gather sub-codebook, split, B'' = [ch|cl|ch], row norms ----
__global__ void k_prep_c(const float* __restrict__ cb, const int* __restrict__ rnd) {
    int k = blockIdx.x;          // 0..K_PAD-1
    int t = threadIdx.x;         // 64 threads x float4
    __shared__ float ssum[2];
    float4 v = make_float4(0.f, 0.f, 0.f, 0.f);
    if (k < K_SUB) v = ((const float4*)(cb + (size_t)rnd[k] * D_DIM))[t];
    __half hx = __float2half_rn(v.x), hy = __float2half_rn(v.y);
    __half hz = __float2half_rn(v.z), hw = __float2half_rn(v.w);
    __half lx = __float2half_rn(v.x - __half2float(hx));
    __half ly = __float2half_rn(v.y - __half2float(hy));
    __half lz = __float2half_rn(v.z - __half2float(hz));
    __half lw = __float2half_rn(v.w - __half2float(hw));
    __half2 h0 = __halves2half2(hx, hy), h1 = __halves2half2(hz, hw);
    __half2 l0 = __halves2half2(lx, ly), l1 = __halves2half2(lz, lw);
    __half2* base = (__half2*)(g_cb2 + (size_t)k * KP + t * 4);
    base[0] = h0; base[1] = h1;                       // ch
    base[128] = l0; base[129] = l1;                   // cl
    base[256] = h0; base[257] = h1;                   // ch
    float s = v.x * v.x + v.y * v.y + v.z * v.z + v.w * v.w;
    #pragma unroll
    for (int o = 16; o; o >>= 1) s += __shfl_down_sync(0xffffffffu, s, o);
    if ((t & 31) == 0) ssum[t >> 5] = s;
    __syncthreads();
    if (t == 0) g_c2[k] = (k < K_SUB) ? (ssum[0] + ssum[1]) : 3.0e38f;
}

// ---------------- kernel 2: HMMA GEMM + argmin ----------------
// CTA tile 128 tokens x 128 cands, K'=768 in 12 chunks of 64 halves.
// 8 warps in 2(m) x 4(n) grid, each warp 64x32 via m16n8k16.
// Dyn smem: A[2][128*64] + B[2][128*64] halves = 64 KB, SW128-swizzled rows.
#define CHUNK_H 64            // halves per K chunk
#define SMEM_AB (128 * CHUNK_H * 2)   // 16 KB per tile-buffer
#define DYN_SMEM (4 * SMEM_AB + 1024)

__global__ void __launch_bounds__(256, 2) k_tc(void) {
    extern __shared__ __align__(16) unsigned char dynraw[];
    char* sb = (char*)(((uintptr_t)dynraw + 1023) & ~(uintptr_t)1023);
    const uint32_t s0 = smem_u32(sb);
    // buffers: A0, A1, B0, B1
    const uint32_t sA[2] = { s0, s0 + SMEM_AB };
    const uint32_t sB[2] = { s0 + 2 * SMEM_AB, s0 + 3 * SMEM_AB };

    __shared__ float c2s[128];
    __shared__ float sd[128][4];
    __shared__ int   si[128][4];

    const int tid = threadIdx.x;
    const int wid = tid >> 5, lane = tid & 31;
    const int wm = wid & 1, wn = wid >> 1;          // 2 x 4 warp grid
    const int lr = lane & 7, lg = lane >> 3;
    const int tokBase = blockIdx.x * 128;
    const int nBase   = blockIdx.y * 128;

    if (tid < 128) c2s[tid] = g_c2[nBase + tid];

    // per-thread cp.async coordinates: idx = q*256+tid -> row=idx>>3, c16=idx&7
    const __half* Ag = g_xb  + (size_t)tokBase * KP;
    const __half* Bg = g_cb2 + (size_t)nBase * KP;

    float acc[4][4][4];
    #pragma unroll
    for (int a = 0; a < 4; a++)
        #pragma unroll
        for (int b = 0; b < 4; b++)
            #pragma unroll
            for (int e = 0; e < 4; e++) acc[a][b][e] = 0.f;

    // ldmatrix lane addresses (byte offsets within a tile-buffer), per fragment set
    // A: row = wm*64 + mf*16 + lr + (lg&1)*8 ; c16 = ks*2 + (lg>>1)
    // B: row = wn*32 + nb*16 + lr + (lg>>1)*8 ; c16 = ks*2 + (lg&1)
    int arow[4], brow[2];
    #pragma unroll
    for (int mf = 0; mf < 4; mf++) arow[mf] = wm * 64 + mf * 16 + lr + ((lg & 1) << 3);
    #pragma unroll
    for (int nb = 0; nb < 2; nb++) brow[nb] = wn * 32 + nb * 16 + lr + ((lg >> 1) << 3);
    const int acol = lg >> 1, bcol = lg & 1;

    auto issue = [&](int ch, int buf) {
        #pragma unroll
        for (int q = 0; q < 4; q++) {
            int idx = q * 256 + tid;
            int row = idx >> 3, c = idx & 7;
            cpa16(sA[buf] + row * 128 + ((c ^ (row & 7)) << 4),
                  Ag + (size_t)row * KP + ch * CHUNK_H + c * 8);
        }
        #pragma unroll
        for (int q = 0; q < 4; q++) {
            int idx = q * 256 + tid;
            int row = idx >> 3, c = idx & 7;
            cpa16(sB[buf] + row * 128 + ((c ^ (row & 7)) << 4),
                  Bg + (size_t)row * KP + ch * CHUNK_H + c * 8);
        }
        CP_COMMIT();
    };

    issue(0, 0);
    #pragma unroll 1
    for (int ch = 0; ch < 12; ++ch) {
        const int buf = ch & 1;
        if (ch < 11) { issue(ch + 1, buf ^ 1); CP_WAIT(1); }
        else         { CP_WAIT(0); }
        __syncthreads();

        #pragma unroll
        for (int ks = 0; ks < 4; ++ks) {
            uint32_t af[4][4], bf[2][4];
            #pragma unroll
            for (int mf = 0; mf < 4; mf++) {
                int r = arow[mf], c16 = ks * 2 + acol;
                ldsm4(af[mf], sA[buf] + r * 128 + ((c16 ^ (r & 7)) << 4));
            }
            #pragma unroll
            for (int nb = 0; nb < 2; nb++) {
                int r = brow[nb], c16 = ks * 2 + bcol;
                ldsm4(bf[nb], sB[buf] + r * 128 + ((c16 ^ (r & 7)) << 4));
            }
            #pragma unroll
            for (int mf = 0; mf < 4; mf++)
                #pragma unroll
                for (int nf = 0; nf < 4; nf++)
                    mma16816(acc[mf][nf], af[mf], bf[nf >> 1][(nf & 1) * 2],
                             bf[nf >> 1][(nf & 1) * 2 + 1]);
        }
        __syncthreads();
    }

    // epilogue: dist = ||c||^2 - 2*dot; per-thread -> quad -> warp -> CTA argmin
    #pragma unroll
    for (int mf = 0; mf < 4; mf++) {
        #pragma unroll
        for (int h = 0; h < 2; h++) {
            int rowL = wm * 64 + mf * 16 + (lane >> 2) + h * 8;
            float best = 3.4e38f; int bi = 0x7fffffff;
            #pragma unroll
            for (int nf = 0; nf < 4; nf++)
                #pragma unroll
                for (int j = 0; j < 2; j++) {
                    int colL = wn * 32 + nf * 8 + (lane & 3) * 2 + j;
                    float d = c2s[colL] - 2.0f * acc[mf][nf][h * 2 + j];
                    int cg = nBase + colL;
                    if (d < best || (d == best && cg < bi)) { best = d; bi = cg; }
                }
            #pragma unroll
            for (int o = 1; o <= 2; o <<= 1) {
                float od = __shfl_xor_sync(0xffffffffu, best, o);
                int   oi = __shfl_xor_sync(0xffffffffu, bi, o);
                if (od < best || (od == best && oi < bi)) { best = od; bi = oi; }
            }
            if ((lane & 3) == 0) { sd[rowL][wn] = best; si[rowL][wn] = bi; }
        }
    }
    __syncthreads();
    if (tid < 128) {
        float best = sd[tid][0]; int bi = si[tid][0];
        #pragma unroll
        for (int w = 1; w < 4; w++) {
            float d = sd[tid][w]; int i2 = si[tid][w];
            if (d < best || (d == best && i2 < bi)) { best = d; bi = i2; }
        }
        g_bestd[blockIdx.y * N_TOK + tokBase + tid] = best;
        g_besti[blockIdx.y * N_TOK + tokBase + tid] = bi;
    }
}

// ---------------- kernel 3: merge cand-tiles ----------------
__global__ void k_merge(const int* __restrict__ rnd, float* __restrict__ out) {
    int t = blockIdx.x * 256 + threadIdx.x;
    float bd = g_bestd[t];
    int   bi = g_besti[t];
    #pragma unroll 1
    for (int s = 1; s < N_YT; ++s) {
        float d = g_bestd[s * N_TOK + t];
        int   i = g_besti[s * N_TOK + t];
        if (d < bd || (d == bd && i < bi)) { bd = d; bi = i; }
    }
    int ci = rnd[bi];
    g_fidx[t] = ci;
    out[OUT_IDX + t] = (float)ci;
}

// ---------------- kernel 4: gather + loss partials ----------------
__global__ void k_gather(const float* __restrict__ x, const float* __restrict__ cb,
                         float* __restrict__ out) {
    __shared__ float red[256];
    int tid = threadIdx.x;
    float s = 0.f;
    #pragma unroll
    for (int j = 0; j < 4; j++) {
        int f = blockIdx.x * 1024 + j * 256 + tid;
        int tok = f >> 6, off = f & 63;
        int ci = g_fidx[tok];
        float4 c = ((const float4*)cb)[(size_t)ci * 64 + off];
        float4 xv = ((const float4*)x)[f];
        ((float4*)out)[f] = c;
        float dx = c.x - xv.x, dy = c.y - xv.y, dz = c.z - xv.z, dw = c.w - xv.w;
        s += dx * dx + dy * dy + dz * dz + dw * dw;
    }
    red[tid] = s;
    __syncthreads();
    for (int o = 128; o; o >>= 1) {
        if (tid < o) red[tid] += red[tid + o];
        __syncthreads();
    }
    if (tid == 0) g_partial[blockIdx.x] = red[0];
}

// ---------------- kernel 5: final loss reduce ----------------
__global__ void k_loss(float* __restrict__ out) {
    __shared__ float red[256];
    int tid = threadIdx.x;
    float s = 0.f;
    for (int j = tid; j < 1024; j += 256) s += g_partial[j];
    red[tid] = s;
    __syncthreads();
    for (int o = 128; o; o >>= 1) {
        if (tid < o) red[tid] += red[tid + o];
        __syncthreads();
    }
    if (tid == 0) out[OUT_LOSS] = red[0] / (float)OUT_TOKENS;
}

// ---------------- launch ----------------
extern "C" void kernel_launch(void* const* d_in, const int* in_sizes, int n_in,
                              void* d_out, int out_size) {
    const float* x   = (const float*)d_in[0];
    const float* cb  = (const float*)d_in[1];
    const int*   rnd = (const int*)d_in[2];
    float* out = (float*)d_out;

    static int smem_set = 0;
    if (!smem_set) {
        cudaFuncSetAttribute(k_tc, cudaFuncAttributeMaxDynamicSharedMemorySize, DYN_SMEM);
        smem_set = 1;
    }

    k_prep_x<<<4096, 256>>>(x);
    k_prep_c<<<K_PAD, 64>>>(cb, rnd);
    k_tc<<<dim3(128, N_YT), 256, DYN_SMEM>>>();
    k_merge<<<64, 256>>>(rnd, out);
    k_gather<<<1024, 256>>>(x, cb, out);
    k_loss<<<1, 256>>>(out);
}

// round 4
// speedup vs baseline: 3.3345x; 1.0300x over previous
#include <cuda_runtime.h>
#include <cuda_fp16.h>
#include <cstdint>

// ---------------- problem constants ----------------
#define N_TOK   16384          // B*S
#define D_DIM   256
#define K_SUB   3686
#define K_PAD   3840           // 30 * 128
#define N_YT    30             // candidate tiles of 128
#define K_STORE 512            // stored K: [hi|lo]
#define OUT_TOKENS  (N_TOK * D_DIM)
#define OUT_LOSS    OUT_TOKENS
#define OUT_IDX     (OUT_TOKENS + 1)

// ---------------- device scratch ----------------
__device__ __align__(16) __half g_xb[N_TOK * K_STORE];    // [xh|xl] 16.8 MB
__device__ __align__(16) __half g_cb2[K_PAD * K_STORE];   // [ch|cl]  3.9 MB
__device__ float g_c2[K_PAD];
__device__ unsigned long long g_best64[N_TOK];            // packed (dist,idx)
__device__ int   g_fidx[N_TOK];
__device__ float g_partial[1024];

// ---------------- PTX helpers ----------------
__device__ __forceinline__ uint32_t smem_u32(const void* p) {
    uint32_t a;
    asm("{ .reg .u64 t; cvta.to.shared.u64 t, %1; cvt.u32.u64 %0, t; }" : "=r"(a) : "l"(p));
    return a;
}
__device__ __forceinline__ void cpa16(uint32_t dst, const void* src) {
    asm volatile("cp.async.cg.shared.global [%0], [%1], 16;" :: "r"(dst), "l"(src));
}
#define CP_COMMIT() asm volatile("cp.async.commit_group;" ::: "memory")
#define CP_WAIT(n)  asm volatile("cp.async.wait_group %0;" :: "n"(n) : "memory")

__device__ __forceinline__ void ldsm4(uint32_t* r, uint32_t a) {
    asm volatile("ldmatrix.sync.aligned.m8n8.x4.shared.b16 {%0,%1,%2,%3}, [%4];"
        : "=r"(r[0]), "=r"(r[1]), "=r"(r[2]), "=r"(r[3]) : "r"(a));
}
__device__ __forceinline__ void mma16816(float* c, const uint32_t* a,
                                         uint32_t b0, uint32_t b1) {
    asm volatile("mma.sync.aligned.m16n8k16.row.col.f32.f16.f16.f32 "
        "{%0,%1,%2,%3}, {%4,%5,%6,%7}, {%8,%9}, {%0,%1,%2,%3};"
        : "+f"(c[0]), "+f"(c[1]), "+f"(c[2]), "+f"(c[3])
        : "r"(a[0]), "r"(a[1]), "r"(a[2]), "r"(a[3]), "r"(b0), "r"(b1));
}

// order-preserving float -> uint32 map (monotone for all finite floats)
__device__ __forceinline__ uint32_t fmap(float f) {
    uint32_t b = __float_as_uint(f);
    return (b & 0x80000000u) ? ~b : (b | 0x80000000u);
}

// ---------------- kernel 1a: split x -> fp16 hi/lo [xh|xl]; init g_best64 ----
__global__ void k_prep_x(const float* __restrict__ x) {
    int i = blockIdx.x * 256 + threadIdx.x;       // float4 index (1M)
    if (i < N_TOK) g_best64[i] = 0xFFFFFFFFFFFFFFFFull;
    int tok = i >> 6, d4 = i & 63;
    float4 v = ((const float4*)x)[i];
    __half hx = __float2half_rn(v.x), hy = __float2half_rn(v.y);
    __half hz = __float2half_rn(v.z), hw = __float2half_rn(v.w);
    __half lx = __float2half_rn(v.x - __half2float(hx));
    __half ly = __float2half_rn(v.y - __half2float(hy));
    __half lz = __float2half_rn(v.z - __half2float(hz));
    __half lw = __float2half_rn(v.w - __half2float(hw));
    __half2* base = (__half2*)(g_xb + (size_t)tok * K_STORE + d4 * 4);
    base[0] = __halves2half2(hx, hy); base[1] = __halves2half2(hz, hw);
    base[128] = __halves2half2(lx, ly); base[129] = __halves2half2(lz, lw);
}

// ---- kernel 1b: gather sub-codebook, split [ch|cl], row norms ----
__global__ void k_prep_c(const float* __restrict__ cb, const int* __restrict__ rnd) {
    int k = blockIdx.x;          // 0..K_PAD-1
    int t = threadIdx.x;         // 64 threads x float4
    __shared__ float ssum[2];
    float4 v = make_float4(0.f, 0.f, 0.f, 0.f);
    if (k < K_SUB) v = ((const float4*)(cb + (size_t)rnd[k] * D_DIM))[t];
    __half hx = __float2half_rn(v.x), hy = __float2half_rn(v.y);
    __half hz = __float2half_rn(v.z), hw = __float2half_rn(v.w);
    __half lx = __float2half_rn(v.x - __half2float(hx));
    __half ly = __float2half_rn(v.y - __half2float(hy));
    __half lz = __float2half_rn(v.z - __half2float(hz));
    __half lw = __float2half_rn(v.w - __half2float(hw));
    __half2* base = (__half2*)(g_cb2 + (size_t)k * K_STORE + t * 4);
    base[0] = __halves2half2(hx, hy); base[1] = __halves2half2(hz, hw);
    base[128] = __halves2half2(lx, ly); base[129] = __halves2half2(lz, lw);
    float s = v.x * v.x + v.y * v.y + v.z * v.z + v.w * v.w;
    #pragma unroll
    for (int o = 16; o; o >>= 1) s += __shfl_down_sync(0xffffffffu, s, o);
    if ((t & 31) == 0) ssum[t >> 5] = s;
    __syncthreads();
    if (t == 0) g_c2[k] = (k < K_SUB) ? (ssum[0] + ssum[1]) : 3.0e38f;
}

// ---------------- kernel 2: HMMA GEMM + argmin + atomic merge ----------------
// CTA tile 128 tokens x 128 cands, virtual K'=768 in 12 chunks of 64 halves:
//   chunks 0-3: xh.ch, 4-7: xh.cl, 8-11: xl.ch  (operands stored dedup at K=512)
// 8 warps in 2(m) x 4(n) grid, each warp 64x32 via m16n8k16.
#define CHUNK_H 64
#define SMEM_AB (128 * CHUNK_H * 2)   // 16 KB per tile-buffer
#define DYN_SMEM (4 * SMEM_AB + 1024)

__global__ void __launch_bounds__(256, 2) k_tc(void) {
    extern __shared__ __align__(16) unsigned char dynraw[];
    char* sb = (char*)(((uintptr_t)dynraw + 1023) & ~(uintptr_t)1023);
    const uint32_t s0 = smem_u32(sb);
    const uint32_t sA[2] = { s0, s0 + SMEM_AB };
    const uint32_t sB[2] = { s0 + 2 * SMEM_AB, s0 + 3 * SMEM_AB };

    __shared__ float c2s[128];
    __shared__ float sd[128][4];
    __shared__ int   si[128][4];

    const int tid = threadIdx.x;
    const int wid = tid >> 5, lane = tid & 31;
    const int wm = wid & 1, wn = wid >> 1;
    const int lr = lane & 7, lg = lane >> 3;
    const int tokBase = blockIdx.x * 128;
    const int nBase   = blockIdx.y * 128;

    if (tid < 128) c2s[tid] = g_c2[nBase + tid];

    const __half* Ag = g_xb  + (size_t)tokBase * K_STORE;
    const __half* Bg = g_cb2 + (size_t)nBase * K_STORE;

    float acc[4][4][4];
    #pragma unroll
    for (int a = 0; a < 4; a++)
        #pragma unroll
        for (int b = 0; b < 4; b++)
            #pragma unroll
            for (int e = 0; e < 4; e++) acc[a][b][e] = 0.f;

    int arow[4], brow[2];
    #pragma unroll
    for (int mf = 0; mf < 4; mf++) arow[mf] = wm * 64 + mf * 16 + lr + ((lg & 1) << 3);
    #pragma unroll
    for (int nb = 0; nb < 2; nb++) brow[nb] = wn * 32 + nb * 16 + lr + ((lg >> 1) << 3);
    const int acol = lg >> 1, bcol = lg & 1;

    // per-chunk column offsets (in halves) into the dedup K=512 storage
    auto issue = [&](int ch, int buf) {
        int aoff = (ch < 8) ? (ch & 3) * CHUNK_H : (256 + (ch & 3) * CHUNK_H);
        int boff = (ch < 4) ? ch * CHUNK_H
                 : (ch < 8) ? (256 + (ch & 3) * CHUNK_H) : (ch & 3) * CHUNK_H;
        #pragma unroll
        for (int q = 0; q < 4; q++) {
            int idx = q * 256 + tid;
            int row = idx >> 3, c = idx & 7;
            cpa16(sA[buf] + row * 128 + ((c ^ (row & 7)) << 4),
                  Ag + (size_t)row * K_STORE + aoff + c * 8);
        }
        #pragma unroll
        for (int q = 0; q < 4; q++) {
            int idx = q * 256 + tid;
            int row = idx >> 3, c = idx & 7;
            cpa16(sB[buf] + row * 128 + ((c ^ (row & 7)) << 4),
                  Bg + (size_t)row * K_STORE + boff + c * 8);
        }
        CP_COMMIT();
    };

    issue(0, 0);
    #pragma unroll 1
    for (int ch = 0; ch < 12; ++ch) {
        const int buf = ch & 1;
        if (ch < 11) { issue(ch + 1, buf ^ 1); CP_WAIT(1); }
        else         { CP_WAIT(0); }
        __syncthreads();

        #pragma unroll
        for (int ks = 0; ks < 4; ++ks) {
            uint32_t af[4][4], bf[2][4];
            #pragma unroll
            for (int mf = 0; mf < 4; mf++) {
                int r = arow[mf], c16 = ks * 2 + acol;
                ldsm4(af[mf], sA[buf] + r * 128 + ((c16 ^ (r & 7)) << 4));
            }
            #pragma unroll
            for (int nb = 0; nb < 2; nb++) {
                int r = brow[nb], c16 = ks * 2 + bcol;
                ldsm4(bf[nb], sB[buf] + r * 128 + ((c16 ^ (r & 7)) << 4));
            }
            #pragma unroll
            for (int mf = 0; mf < 4; mf++)
                #pragma unroll
                for (int nf = 0; nf < 4; nf++)
                    mma16816(acc[mf][nf], af[mf], bf[nf >> 1][(nf & 1) * 2],
                             bf[nf >> 1][(nf & 1) * 2 + 1]);
        }
        __syncthreads();
    }

    // epilogue: dist = ||c||^2 - 2*dot; thread -> quad -> warp-col -> CTA -> atomic
    #pragma unroll
    for (int mf = 0; mf < 4; mf++) {
        #pragma unroll
        for (int h = 0; h < 2; h++) {
            int rowL = wm * 64 + mf * 16 + (lane >> 2) + h * 8;
            float best = 3.4e38f; int bi = 0x7fffffff;
            #pragma unroll
            for (int nf = 0; nf < 4; nf++)
                #pragma unroll
                for (int j = 0; j < 2; j++) {
                    int colL = wn * 32 + nf * 8 + (lane & 3) * 2 + j;
                    float d = c2s[colL] - 2.0f * acc[mf][nf][h * 2 + j];
                    int cg = nBase + colL;
                    if (d < best || (d == best && cg < bi)) { best = d; bi = cg; }
                }
            #pragma unroll
            for (int o = 1; o <= 2; o <<= 1) {
                float od = __shfl_xor_sync(0xffffffffu, best, o);
                int   oi = __shfl_xor_sync(0xffffffffu, bi, o);
                if (od < best || (od == best && oi < bi)) { best = od; bi = oi; }
            }
            if ((lane & 3) == 0) { sd[rowL][wn] = best; si[rowL][wn] = bi; }
        }
    }
    __syncthreads();
    if (tid < 128) {
        float best = sd[tid][0]; int bi = si[tid][0];
        #pragma unroll
        for (int w = 1; w < 4; w++) {
            float d = sd[tid][w]; int i2 = si[tid][w];
            if (d < best || (d == best && i2 < bi)) { best = d; bi = i2; }
        }
        unsigned long long pk = ((unsigned long long)fmap(best) << 32) | (uint32_t)bi;
        atomicMin(&g_best64[tokBase + tid], pk);
    }
}

// ---------------- kernel 3: resolve packed argmin -> codebook index ----------------
__global__ void k_resolve(const int* __restrict__ rnd, float* __restrict__ out) {
    int t = blockIdx.x * 256 + threadIdx.x;
    int bi = (int)(unsigned)(g_best64[t] & 0xFFFFFFFFull);
    int ci = rnd[bi];
    g_fidx[t] = ci;
    out[OUT_IDX + t] = (float)ci;
}

// ---------------- kernel 4: gather + loss partials ----------------
__global__ void k_gather(const float* __restrict__ x, const float* __restrict__ cb,
                         float* __restrict__ out) {
    __shared__ float red[256];
    int tid = threadIdx.x;
    float s = 0.f;
    #pragma unroll
    for (int j = 0; j < 4; j++) {
        int f = blockIdx.x * 1024 + j * 256 + tid;
        int tok = f >> 6, off = f & 63;
        int ci = g_fidx[tok];
        float4 c = ((const float4*)cb)[(size_t)ci * 64 + off];
        float4 xv = ((const float4*)x)[f];
        ((float4*)out)[f] = c;
        float dx = c.x - xv.x, dy = c.y - xv.y, dz = c.z - xv.z, dw = c.w - xv.w;
        s += dx * dx + dy * dy + dz * dz + dw * dw;
    }
    red[tid] = s;
    __syncthreads();
    for (int o = 128; o; o >>= 1) {
        if (tid < o) red[tid] += red[tid + o];
        __syncthreads();
    }
    if (tid == 0) g_partial[blockIdx.x] = red[0];
}

// ---------------- kernel 5: final loss reduce ----------------
__global__ void k_loss(float* __restrict__ out) {
    __shared__ float red[256];
    int tid = threadIdx.x;
    float s = 0.f;
    for (int j = tid; j < 1024; j += 256) s += g_partial[j];
    red[tid] = s;
    __syncthreads();
    for (int o = 128; o; o >>= 1) {
        if (tid < o) red[tid] += red[tid + o];
        __syncthreads();
    }
    if (tid == 0) out[OUT_LOSS] = red[0] / (float)OUT_TOKENS;
}

// ---------------- launch ----------------
extern "C" void kernel_launch(void* const* d_in, const int* in_sizes, int n_in,
                              void* d_out, int out_size) {
    const float* x   = (const float*)d_in[0];
    const float* cb  = (const float*)d_in[1];
    const int*   rnd = (const int*)d_in[2];
    float* out = (float*)d_out;

    static int smem_set = 0;
    if (!smem_set) {
        cudaFuncSetAttribute(k_tc, cudaFuncAttributeMaxDynamicSharedMemorySize, DYN_SMEM);
        smem_set = 1;
    }

    k_prep_x<<<4096, 256>>>(x);
    k_prep_c<<<K_PAD, 64>>>(cb, rnd);
    k_tc<<<dim3(128, N_YT), 256, DYN_SMEM>>>();
    k_resolve<<<64, 256>>>(rnd, out);
    k_gather<<<1024, 256>>>(x, cb, out);
    k_loss<<<1, 256>>>(out);
}